// round 15
// baseline (speedup 1.0000x reference)
#include <cuda_runtime.h>
#include <cuda_bf16.h>
#include <math.h>
#include <stdint.h>

// Problem constants
#define BB 8
#define CC 128
#define HH 96
#define WW 96
#define PP (HH*WW)       // 9216
#define NG 16            // groups
#define CPG 8            // channels per group
#define NBLK 288         // df blocks (BB*PP/256)
#define BPB 36           // df blocks per batch
#define NBS 72           // stats blocks (BB*PP/1024)
#define BPBS 9           // stats blocks per batch

// ---------------- scratch (device globals; no allocs allowed) ----------------
__device__ float g_avg [BB*PP];
__device__ float g_invn[BB*PP];
__device__ float g_df  [BB*PP];
__device__ float g_ps  [NBS*NG];
__device__ float g_pss [NBS*NG];
__device__ float g_pmn [NBLK];
__device__ float g_pmx [NBLK];
__device__ uint4 g_w1f [16*8*32];          // w1 bf16x2 in mma-fragment order
__device__ uint4 g_w2f [8*16*32];          // w2 bf16x2 in mma-fragment order

__device__ __forceinline__ int refl(int i) {
    return i < 0 ? -i : (i >= HH ? 2*HH - 2 - i : i);
}

__device__ __forceinline__ unsigned packbf(float lo, float hi) {
    unsigned d;
    asm("cvt.rn.bf16x2.f32 %0, %1, %2;" : "=r"(d) : "f"(hi), "f"(lo));
    return d;
}

// ---------------- K1: per-pixel avg & inv-norm, per-(b,g) partial sums -------
// 4 pixels/thread (float4); blocks >= NBS convert w1/w2 to fragment layout.
__global__ void k_stats(const float* __restrict__ x,
                        const float* __restrict__ w1,
                        const float* __restrict__ w2) {
    int tid = threadIdx.x;
    if (blockIdx.x >= NBS) {
        int idx = (blockIdx.x - NBS) * 256 + tid;      // 0..8191
        int lane = idx & 31, lk = lane & 3, lm = lane >> 2;
        int kw;
        if (idx < 4096) {                              // w1: 16 m-groups x 8 steps
            int m16 = idx >> 8, st = (idx >> 5) & 7;
            int mr = m16*16 + lm; kw = st*8;
            uint4 v;
            v.x = packbf(w1[mr*128     + 2*(kw+lk)],   w1[mr*128     + 2*(kw+lk)+1]);
            v.y = packbf(w1[(mr+8)*128 + 2*(kw+lk)],   w1[(mr+8)*128 + 2*(kw+lk)+1]);
            v.z = packbf(w1[mr*128     + 2*(kw+4+lk)], w1[mr*128     + 2*(kw+4+lk)+1]);
            v.w = packbf(w1[(mr+8)*128 + 2*(kw+4+lk)], w1[(mr+8)*128 + 2*(kw+4+lk)+1]);
            g_w1f[idx] = v;
        } else {                                       // w2: 8 m-groups x 16 steps
            int j = idx - 4096;
            int m16 = j >> 9, st = (j >> 5) & 15;
            int mr = m16*16 + lm; kw = st*8;
            uint4 v;
            v.x = packbf(w2[mr*256     + 2*(kw+lk)],   w2[mr*256     + 2*(kw+lk)+1]);
            v.y = packbf(w2[(mr+8)*256 + 2*(kw+lk)],   w2[(mr+8)*256 + 2*(kw+lk)+1]);
            v.z = packbf(w2[mr*256     + 2*(kw+4+lk)], w2[mr*256     + 2*(kw+4+lk)+1]);
            v.w = packbf(w2[(mr+8)*256 + 2*(kw+4+lk)], w2[(mr+8)*256 + 2*(kw+4+lk)+1]);
            g_w2f[j] = v;
        }
        return;
    }

    int idx = (blockIdx.x * 256 + tid) * 4;  // (b,p), 4 consecutive pixels
    int b = idx / PP;                        // blocks batch-aligned (PP=9*1024)
    const float* xb = x + (size_t)b * CC * PP + (idx - b*PP);
    int lane = tid & 31;

    __shared__ float s_gs[NG], s_gss[NG];
    if (tid < NG) { s_gs[tid] = 0.f; s_gss[tid] = 0.f; }
    __syncthreads();

    float4 sum4 = make_float4(0.f, 0.f, 0.f, 0.f);
    float4 ssq4 = make_float4(0.f, 0.f, 0.f, 0.f);
    float gsA[NG], gssA[NG];

    #pragma unroll
    for (int g = 0; g < NG; g++) {
        float gs = 0.f, gss = 0.f;
        #pragma unroll
        for (int cc = 0; cc < CPG; cc++) {
            float4 v = *(const float4*)&xb[(size_t)(g*CPG + cc) * PP];
            sum4.x += v.x; sum4.y += v.y; sum4.z += v.z; sum4.w += v.w;
            ssq4.x += v.x*v.x; ssq4.y += v.y*v.y;
            ssq4.z += v.z*v.z; ssq4.w += v.w*v.w;
            gs  += (v.x + v.y) + (v.z + v.w);
            gss += (v.x*v.x + v.y*v.y) + (v.z*v.z + v.w*v.w);
        }
        gsA[g] = gs; gssA[g] = gss;
    }

    // per-pixel outputs (float4 stores)
    float4 av, iv;
    av.x = sum4.x * (1.f/128.f); av.y = sum4.y * (1.f/128.f);
    av.z = sum4.z * (1.f/128.f); av.w = sum4.w * (1.f/128.f);
    iv.x = 1.f / fmaxf(sqrtf(ssq4.x), 1e-12f);
    iv.y = 1.f / fmaxf(sqrtf(ssq4.y), 1e-12f);
    iv.z = 1.f / fmaxf(sqrtf(ssq4.z), 1e-12f);
    iv.w = 1.f / fmaxf(sqrtf(ssq4.w), 1e-12f);
    *(float4*)&g_avg [idx] = av;
    *(float4*)&g_invn[idx] = iv;

    // deferred group reductions (no longer throttle the load loop)
    #pragma unroll
    for (int g = 0; g < NG; g++) {
        float gs = gsA[g], gss = gssA[g];
        #pragma unroll
        for (int off = 16; off; off >>= 1) {
            gs  += __shfl_xor_sync(0xffffffffu, gs,  off);
            gss += __shfl_xor_sync(0xffffffffu, gss, off);
        }
        if (lane == 0) { atomicAdd(&s_gs[g], gs); atomicAdd(&s_gss[g], gss); }
    }
    __syncthreads();
    if (tid < NG) {
        g_ps [blockIdx.x*NG + tid] = s_gs [tid];
        g_pss[blockIdx.x*NG + tid] = s_gss[tid];
    }
}

// ---------------- K2: laplacian of avg (zero pad), per-block min/max ---------
__global__ void k_df() {
    int tid = threadIdx.x;
    int idx = blockIdx.x * 256 + tid;
    int b = idx / PP;
    int p = idx - b*PP;
    int y = p / WW, xq = p - y*WW;
    float c = g_avg[idx];
    float up = (y > 0)      ? g_avg[idx - WW] : 0.f;
    float dn = (y < HH-1)   ? g_avg[idx + WW] : 0.f;
    float lf = (xq > 0)     ? g_avg[idx - 1]  : 0.f;
    float rt = (xq < WW-1)  ? g_avg[idx + 1]  : 0.f;
    float df = fabsf(4.f*c - up - dn - lf - rt);
    g_df[idx] = df;

    __shared__ float smn[256], smx[256];
    smn[tid] = df; smx[tid] = df;
    __syncthreads();
    for (int s = 128; s; s >>= 1) {
        if (tid < s) {
            smn[tid] = fminf(smn[tid], smn[tid+s]);
            smx[tid] = fmaxf(smx[tid], smx[tid+s]);
        }
        __syncthreads();
    }
    if (tid == 0) { g_pmn[blockIdx.x] = smn[0]; g_pmx[blockIdx.x] = smx[0]; }
}

// ======= K3: FUSED IPG core + GroupNorm + FFN (single kernel) ================
#define TW 32
#define TH 4
#define ROWW 34          // TW+2
#define TILE2 204        // (TH+2)*ROWW
#define PSTR 12          // words per position: 8 ch + 4 pad
#define NPIX 128         // pixels per CTA
#define ESTR 68          // Es words per pixel row (64 k-pairs + 4 pad)
#define HSTR 132         // Hs words per pixel row (128 k-pairs + 4 pad)
#define STSZ (2*2*TILE2*PSTR)   // 9792 floats for s_t
#define SMEM_FUSED ((128*ESTR + STSZ) * 4)

#define CE(a_,b_) do { \
    if ((sv[b_] > sv[a_]) || (sv[b_] == sv[a_] && si[b_] < si[a_])) { \
        float t_ = sv[a_]; sv[a_] = sv[b_]; sv[b_] = t_; \
        int u_ = si[a_]; si[a_] = si[b_]; si[b_] = u_; } \
} while (0)

#define MMA_BF16(C, A, B2) asm volatile( \
    "mma.sync.aligned.m16n8k16.row.col.f32.bf16.bf16.f32 " \
    "{%0,%1,%2,%3}, {%4,%5,%6,%7}, {%8,%9}, {%0,%1,%2,%3};\n" \
    : "+f"((C)[0]), "+f"((C)[1]), "+f"((C)[2]), "+f"((C)[3]) \
    : "r"((A)[0]), "r"((A)[1]), "r"((A)[2]), "r"((A)[3]), \
      "r"((B2)[0]), "r"((B2)[1]))

__global__ void __launch_bounds__(256, 2) k_fused(const float* __restrict__ x,
                                                  const float* __restrict__ gnw,
                                                  const float* __restrict__ gnb,
                                                  const float* __restrict__ b1,
                                                  const float* __restrict__ b2,
                                                  float* __restrict__ out) {
    extern __shared__ float sm[];
    unsigned* EsU = (unsigned*)sm;             // [128][ESTR]
    float*    s_t = sm + 128*ESTR;             // union: s_t | Hs
    unsigned* HsU = (unsigned*)(sm + 128*ESTR);

    __shared__ float s_red[NPIX][10];
    __shared__ float s_inv[TILE2];
    __shared__ float s_mean[NG], s_istd[NG];
    __shared__ float s_gnw[CC], s_gnb[CC];
    __shared__ float s_mn, s_mx;

    int b = blockIdx.z;
    int x0 = blockIdx.x * TW, y0 = blockIdx.y * TH;
    int tx = threadIdx.x, ty = threadIdx.y, zz = threadIdx.z;
    int tid = ty * TW + tx;                 // pixel 0..127
    int ft  = zz * NPIX + tid;              // flat 0..255

    // inline GN-stat reduction
    if (ft < NG) {
        float s = 0.f, ss = 0.f;
        for (int l = 0; l < BPBS; l++) {
            s  += g_ps [(b*BPBS + l)*NG + ft];
            ss += g_pss[(b*BPBS + l)*NG + ft];
        }
        const float N = (float)(CPG * PP);
        float mean = s / N;
        s_mean[ft] = mean;
        s_istd[ft] = rsqrtf(ss / N - mean*mean + 1e-5f);
    } else if (ft == NG) {
        float mn = g_pmn[b*BPB];
        for (int l = 1; l < BPB; l++) mn = fminf(mn, g_pmn[b*BPB + l]);
        s_mn = mn;
    } else if (ft == NG + 1) {
        float mx = g_pmx[b*BPB];
        for (int l = 1; l < BPB; l++) mx = fmaxf(mx, g_pmx[b*BPB + l]);
        s_mx = mx;
    }
    if (ft < CC) { s_gnw[ft] = gnw[ft]; s_gnb[ft] = gnb[ft]; }

    // reflected global offsets for this half's fill positions
    int gp[2];
    #pragma unroll
    for (int j = 0; j < 2; j++) {
        int i = tid + NPIX*j;
        if (i < TILE2) {
            int yy = i / ROWW, xx = i - yy*ROWW;
            gp[j] = refl(y0 + yy - 1)*WW + refl(x0 + xx - 1);
        }
    }
    if (zz == 0) {
        #pragma unroll
        for (int j = 0; j < 2; j++) {
            int i = tid + NPIX*j;
            if (i < TILE2) s_inv[i] = g_invn[b*PP + gp[j]];
        }
    }

    const float* xbase = x + (size_t)(b*CC + zz*64) * PP;  // this half's channels

    float pv[2][8];
    auto ldchunk = [&](int ch) {
        const float* xb = xbase + (size_t)(ch*8) * PP;
        #pragma unroll
        for (int j = 0; j < 2; j++) {
            int i = tid + NPIX*j;
            if (i < TILE2) {
                #pragma unroll
                for (int c = 0; c < 8; c++) pv[j][c] = xb[(size_t)c*PP + gp[j]];
            }
        }
    };
    auto stchunk = [&](int buf) {
        #pragma unroll
        for (int j = 0; j < 2; j++) {
            int i = tid + NPIX*j;
            if (i < TILE2) {
                float4 a  = make_float4(pv[j][0], pv[j][1], pv[j][2], pv[j][3]);
                float4 c4 = make_float4(pv[j][4], pv[j][5], pv[j][6], pv[j][7]);
                *(float4*)&s_t[(zz*2 + buf)*(TILE2*PSTR) + i*PSTR]     = a;
                *(float4*)&s_t[(zz*2 + buf)*(TILE2*PSTR) + i*PSTR + 4] = c4;
            }
        }
    };

    int base9[9];
    #pragma unroll
    for (int dy = 0; dy < 3; dy++)
        #pragma unroll
        for (int dx = 0; dx < 3; dx++)
            base9[dy*3+dx] = ((ty+dy)*ROWW + tx+dx)*PSTR;

    // ---------------- pass 1: partial dots over this half's 64 channels ------
    float dots[9];
    #pragma unroll
    for (int j = 0; j < 9; j++) dots[j] = 0.f;

    ldchunk(0); stchunk(0);
    __syncthreads();
    for (int ch = 0; ch < 8; ch++) {
        int cur = ch & 1;
        if (ch < 7) ldchunk(ch + 1);
        #pragma unroll
        for (int half = 0; half < 2; half++) {
            float4 t9[9];
            #pragma unroll
            for (int j = 0; j < 9; j++)
                t9[j] = *(float4*)&s_t[(zz*2 + cur)*(TILE2*PSTR) + base9[j] + half*4];
            float4 v = t9[4];
            #pragma unroll
            for (int j = 0; j < 9; j++)
                dots[j] += v.x*t9[j].x + v.y*t9[j].y + v.z*t9[j].z + v.w*t9[j].w;
        }
        if (ch < 7) stchunk(cur ^ 1);
        __syncthreads();
    }

    // combine halves
    if (zz == 1) {
        #pragma unroll
        for (int j = 0; j < 9; j++) s_red[tid][j] = dots[j];
    }
    __syncthreads();
    if (zz == 0) {
        #pragma unroll
        for (int j = 0; j < 9; j++) { dots[j] += s_red[tid][j]; s_red[tid][j] = dots[j]; }
    }
    __syncthreads();
    if (zz == 1) {
        #pragma unroll
        for (int j = 0; j < 9; j++) dots[j] = s_red[tid][j];
    }

    float invc = s_inv[(ty+1)*ROWW + tx + 1];
    float sims[9];
    #pragma unroll
    for (int j = 0; j < 9; j++) {
        int dy = j / 3, dx = j - dy*3;
        sims[j] = dots[j] * invc * s_inv[(ty+dy)*ROWW + tx + dx];
    }

    int p = (y0 + ty) * WW + x0 + tx;
    float df = g_df[b*PP + p];
    float dn = (df - s_mn) / (s_mx - s_mn + 1e-8f);
    int k = 1 + (int)rintf(dn * 7.f);
    if (k < 1) k = 1; if (k > 8) k = 8;

    float sv[9]; int si[9];
    #pragma unroll
    for (int j = 0; j < 9; j++) { sv[j] = sims[j]; si[j] = j; }
    CE(0,3); CE(1,7); CE(2,5); CE(4,8);
    CE(0,7); CE(2,4); CE(3,8); CE(5,6);
    CE(0,2); CE(1,3); CE(4,5); CE(7,8);
    CE(1,4); CE(3,6); CE(5,7);
    CE(0,1); CE(2,4); CE(3,5); CE(6,8);
    CE(2,3); CE(4,5); CE(6,7);
    CE(1,2); CE(3,4); CE(5,6);

    float ts = sv[0]; int tix = si[0];
    #pragma unroll
    for (int r = 0; r < 9; r++) { if (r == k-1) { ts = sv[r]; tix = si[r]; } }

    float wj[9]; float ws = 0.f;
    #pragma unroll
    for (int j = 0; j < 9; j++) {
        bool sel = (sims[j] > ts) || (sims[j] == ts && j <= tix);
        wj[j] = sel ? expf(sims[j]) : 0.f;
        ws += wj[j];
    }
    float iws = 1.f / ws;
    #pragma unroll
    for (int j = 0; j < 9; j++) wj[j] *= iws;

    // ---- pass 2: enhanced -> out (fp32, residual) + Es (bf16 pairs) ---------
    ldchunk(0); stchunk(0);
    __syncthreads();
    for (int ch = 0; ch < 8; ch++) {
        int cur = ch & 1;
        if (ch < 7) ldchunk(ch + 1);
        int gidx = zz*8 + ch;
        float gm = s_mean[gidx], gi = s_istd[gidx];
        unsigned wbuf[4];
        #pragma unroll
        for (int half = 0; half < 2; half++) {
            float4 t9[9];
            #pragma unroll
            for (int j = 0; j < 9; j++)
                t9[j] = *(float4*)&s_t[(zz*2 + cur)*(TILE2*PSTR) + base9[j] + half*4];
            float4 acc = make_float4(0.f, 0.f, 0.f, 0.f);
            #pragma unroll
            for (int j = 0; j < 9; j++) {
                acc.x += wj[j]*t9[j].x; acc.y += wj[j]*t9[j].y;
                acc.z += wj[j]*t9[j].z; acc.w += wj[j]*t9[j].w;
            }
            float4 ctr = t9[4];
            int c = zz*64 + ch*8 + half*4;
            float e0 = acc.x + (ctr.x - gm)*gi*s_gnw[c]   + s_gnb[c];
            float e1 = acc.y + (ctr.y - gm)*gi*s_gnw[c+1] + s_gnb[c+1];
            float e2 = acc.z + (ctr.z - gm)*gi*s_gnw[c+2] + s_gnb[c+2];
            float e3 = acc.w + (ctr.w - gm)*gi*s_gnw[c+3] + s_gnb[c+3];
            float* dst = &out[(size_t)(b*CC + c) * PP + p];
            dst[0] = e0; dst[PP] = e1; dst[2*PP] = e2; dst[3*PP] = e3;
            wbuf[half*2]     = packbf(e0, e1);
            wbuf[half*2 + 1] = packbf(e2, e3);
        }
        *(uint4*)&EsU[tid*ESTR + zz*32 + ch*4] = *(uint4*)wbuf;
        if (ch < 7) stchunk(cur ^ 1);
        __syncthreads();
    }
    // s_t now dead; EsU complete and visible. Union region becomes Hs.

    // ==================== FFN phase (two 64-pixel halves) ====================
    int warp = ft >> 5, lane = ft & 31;
    int lm = lane >> 2, lk = lane & 3;

    for (int h = 0; h < 2; h++) {
        const unsigned* EsH = EsU + h*64*ESTR;

        // ---- GEMM1: 8 warps, warp tile 32(M) x 64(N) ----
        int wm1 = warp * 32;
        int m16a = warp * 2;
        float c1[2][8][4];
        #pragma unroll
        for (int mt = 0; mt < 2; mt++)
            #pragma unroll
            for (int nt = 0; nt < 8; nt++)
                #pragma unroll
                for (int q = 0; q < 4; q++) c1[mt][nt][q] = 0.f;

        #pragma unroll
        for (int st = 0; st < 8; st++) {
            int kw = st * 8;
            unsigned a[2][4], bw[8][2];
            *(uint4*)a[0] = g_w1f[((m16a    )*8 + st)*32 + lane];
            *(uint4*)a[1] = g_w1f[((m16a + 1)*8 + st)*32 + lane];
            #pragma unroll
            for (int nt = 0; nt < 8; nt++) {
                int nc = nt*8 + lm;
                bw[nt][0] = EsH[nc*ESTR + kw + lk];
                bw[nt][1] = EsH[nc*ESTR + kw + 4 + lk];
            }
            #pragma unroll
            for (int mt = 0; mt < 2; mt++)
                #pragma unroll
                for (int nt = 0; nt < 8; nt++)
                    MMA_BF16(c1[mt][nt], a[mt], bw[nt]);
        }

        // ---- H: bias + relu, pack row pairs via shfl, store n-major bf16 ----
        #pragma unroll
        for (int mt = 0; mt < 2; mt++) {
            int mr = wm1 + mt*16 + lm;
            float bi0 = b1[mr], bi1 = b1[mr + 8];
            #pragma unroll
            for (int nt = 0; nt < 8; nt++) {
                float v0 = fmaxf(c1[mt][nt][0] + bi0, 0.f);
                float v1 = fmaxf(c1[mt][nt][1] + bi0, 0.f);
                float v2 = fmaxf(c1[mt][nt][2] + bi1, 0.f);
                float v3 = fmaxf(c1[mt][nt][3] + bi1, 0.f);
                float p0 = __shfl_xor_sync(0xffffffffu, v0, 4);
                float p1 = __shfl_xor_sync(0xffffffffu, v1, 4);
                float p2 = __shfl_xor_sync(0xffffffffu, v2, 4);
                float p3 = __shfl_xor_sync(0xffffffffu, v3, 4);
                if (!(lm & 1)) {
                    int colA = nt*8 + 2*lk;
                    int w0 = mr >> 1;
                    HsU[colA    *HSTR + w0]     = packbf(v0, p0);
                    HsU[(colA+1)*HSTR + w0]     = packbf(v1, p1);
                    HsU[colA    *HSTR + w0 + 4] = packbf(v2, p2);
                    HsU[(colA+1)*HSTR + w0 + 4] = packbf(v3, p3);
                }
            }
        }
        __syncthreads();

        // ---- GEMM2: 8 warps, warp tile 16(M) x 64(N), K=256 ----
        int wm2 = warp * 16;
        int m16b = warp;
        float c2[8][4];
        #pragma unroll
        for (int nt = 0; nt < 8; nt++)
            #pragma unroll
            for (int q = 0; q < 4; q++) c2[nt][q] = 0.f;

        #pragma unroll
        for (int st = 0; st < 16; st++) {
            int kw = st * 8;
            unsigned a[4], bw[8][2];
            *(uint4*)a = g_w2f[(m16b*16 + st)*32 + lane];
            #pragma unroll
            for (int nt = 0; nt < 8; nt++) {
                int nc = nt*8 + lm;
                bw[nt][0] = HsU[nc*HSTR + kw + lk];
                bw[nt][1] = HsU[nc*HSTR + kw + 4 + lk];
            }
            #pragma unroll
            for (int nt = 0; nt < 8; nt++)
                MMA_BF16(c2[nt], a, bw[nt]);
        }

        // ---- epilogue: out = E(parked) + ffn + b2 ----
        {
            int mr = wm2 + lm;
            float bi0 = b2[mr], bi1 = b2[mr + 8];
            #pragma unroll
            for (int nt = 0; nt < 8; nt++) {
                int col = nt*8 + 2*lk;
                int lp = h*64 + col;
                int p0 = (y0 + (lp >> 5))*WW + x0 + (lp & 31);
                size_t o0 = (size_t)(b*CC + mr) * PP + p0;
                size_t o1 = o0 + (size_t)8 * PP;
                float2 e0 = *(const float2*)&out[o0];
                float2 e1 = *(const float2*)&out[o1];
                float2 v0, v1;
                v0.x = c2[nt][0] + bi0 + e0.x;
                v0.y = c2[nt][1] + bi0 + e0.y;
                v1.x = c2[nt][2] + bi1 + e1.x;
                v1.y = c2[nt][3] + bi1 + e1.y;
                *(float2*)&out[o0] = v0;
                *(float2*)&out[o1] = v1;
            }
        }
        __syncthreads();   // Hs free for next half
    }
}

// ---------------- launch ----------------
extern "C" void kernel_launch(void* const* d_in, const int* in_sizes, int n_in,
                              void* d_out, int out_size) {
    const float* x   = (const float*)d_in[0];
    const float* gnw = (const float*)d_in[1];
    const float* gnb = (const float*)d_in[2];
    const float* w1  = (const float*)d_in[3];
    const float* b1  = (const float*)d_in[4];
    const float* w2  = (const float*)d_in[5];
    const float* b2  = (const float*)d_in[6];
    float* out = (float*)d_out;

    cudaFuncSetAttribute(k_fused, cudaFuncAttributeMaxDynamicSharedMemorySize, SMEM_FUSED);

    k_stats<<<NBS + 32, 256>>>(x, w1, w2);             // +32 blocks: W->frag bf16
    k_df   <<<NBLK, 256>>>();
    k_fused<<<dim3(WW/TW, HH/TH, BB), dim3(TW, TH, 2), SMEM_FUSED>>>(
        x, gnw, gnb, b1, b2, out);
}

// round 16
// speedup vs baseline: 1.1154x; 1.1154x over previous
#include <cuda_runtime.h>
#include <cuda_bf16.h>
#include <math.h>
#include <stdint.h>

// Problem constants
#define BB 8
#define CC 128
#define HH 96
#define WW 96
#define PP (HH*WW)       // 9216
#define NG 16            // groups
#define CPG 8            // channels per group
#define NBLK 288         // stats/df blocks (BB*PP/256)
#define BPB 36           // blocks per batch (PP/256)

// ---------------- scratch (device globals; no allocs allowed) ----------------
__device__ float g_avg [BB*PP];
__device__ float g_invn[BB*PP];
__device__ float g_df  [BB*PP];
__device__ float g_ps  [NBLK*NG];
__device__ float g_pss [NBLK*NG];
__device__ float g_pmn [NBLK];
__device__ float g_pmx [NBLK];
__device__ uint4 g_w1f [16*8*32];          // w1 bf16x2 in mma-fragment order
__device__ uint4 g_w2f [8*16*32];          // w2 bf16x2 in mma-fragment order

__device__ __forceinline__ int refl(int i) {
    return i < 0 ? -i : (i >= HH ? 2*HH - 2 - i : i);
}

__device__ __forceinline__ unsigned packbf(float lo, float hi) {
    unsigned d;
    asm("cvt.rn.bf16x2.f32 %0, %1, %2;" : "=r"(d) : "f"(hi), "f"(lo));
    return d;
}

// ---------------- K1: per-pixel avg & inv-norm, per-(b,g) partial sums -------
// 1 pixel/thread, 288 blocks; group reductions DEFERRED past the load sweep.
// blocks >= NBLK convert w1/w2 to bf16x2 fragment layout instead.
__global__ void k_stats(const float* __restrict__ x,
                        const float* __restrict__ w1,
                        const float* __restrict__ w2) {
    int tid = threadIdx.x;
    if (blockIdx.x >= NBLK) {
        int idx = (blockIdx.x - NBLK) * 256 + tid;     // 0..8191
        int lane = idx & 31, lk = lane & 3, lm = lane >> 2;
        int kw;
        if (idx < 4096) {                              // w1: 16 m-groups x 8 steps
            int m16 = idx >> 8, st = (idx >> 5) & 7;
            int mr = m16*16 + lm; kw = st*8;
            uint4 v;
            v.x = packbf(w1[mr*128     + 2*(kw+lk)],   w1[mr*128     + 2*(kw+lk)+1]);
            v.y = packbf(w1[(mr+8)*128 + 2*(kw+lk)],   w1[(mr+8)*128 + 2*(kw+lk)+1]);
            v.z = packbf(w1[mr*128     + 2*(kw+4+lk)], w1[mr*128     + 2*(kw+4+lk)+1]);
            v.w = packbf(w1[(mr+8)*128 + 2*(kw+4+lk)], w1[(mr+8)*128 + 2*(kw+4+lk)+1]);
            g_w1f[idx] = v;
        } else {                                       // w2: 8 m-groups x 16 steps
            int j = idx - 4096;
            int m16 = j >> 9, st = (j >> 5) & 15;
            int mr = m16*16 + lm; kw = st*8;
            uint4 v;
            v.x = packbf(w2[mr*256     + 2*(kw+lk)],   w2[mr*256     + 2*(kw+lk)+1]);
            v.y = packbf(w2[(mr+8)*256 + 2*(kw+lk)],   w2[(mr+8)*256 + 2*(kw+lk)+1]);
            v.z = packbf(w2[mr*256     + 2*(kw+4+lk)], w2[mr*256     + 2*(kw+4+lk)+1]);
            v.w = packbf(w2[(mr+8)*256 + 2*(kw+4+lk)], w2[(mr+8)*256 + 2*(kw+4+lk)+1]);
            g_w2f[j] = v;
        }
        return;
    }

    int idx = blockIdx.x * 256 + tid;        // (b,p)
    int b = idx / PP;
    const float* xb = x + (size_t)b * CC * PP + (idx - b*PP);
    int lane = tid & 31;

    __shared__ float s_gs[NG], s_gss[NG];
    if (tid < NG) { s_gs[tid] = 0.f; s_gss[tid] = 0.f; }
    __syncthreads();

    float sum = 0.f, ssq = 0.f;
    float gsA[NG], gssA[NG];
    #pragma unroll
    for (int g = 0; g < NG; g++) {
        float gs = 0.f, gss = 0.f;
        #pragma unroll
        for (int cc = 0; cc < CPG; cc++) {
            float v = xb[(size_t)(g*CPG + cc) * PP];
            gs += v; gss += v*v;
        }
        sum += gs; ssq += gss;
        gsA[g] = gs; gssA[g] = gss;
    }

    g_avg [idx] = sum * (1.f/128.f);
    g_invn[idx] = 1.f / fmaxf(sqrtf(ssq), 1e-12f);

    // deferred group reductions (after the load sweep -> full MLP)
    #pragma unroll
    for (int g = 0; g < NG; g++) {
        float gs = gsA[g], gss = gssA[g];
        #pragma unroll
        for (int off = 16; off; off >>= 1) {
            gs  += __shfl_xor_sync(0xffffffffu, gs,  off);
            gss += __shfl_xor_sync(0xffffffffu, gss, off);
        }
        if (lane == 0) { atomicAdd(&s_gs[g], gs); atomicAdd(&s_gss[g], gss); }
    }
    __syncthreads();
    if (tid < NG) {
        g_ps [blockIdx.x*NG + tid] = s_gs [tid];
        g_pss[blockIdx.x*NG + tid] = s_gss[tid];
    }
}

// ---------------- K2: laplacian of avg (zero pad), per-block min/max ---------
__global__ void k_df() {
    int tid = threadIdx.x;
    int idx = blockIdx.x * 256 + tid;
    int b = idx / PP;
    int p = idx - b*PP;
    int y = p / WW, xq = p - y*WW;
    float c = g_avg[idx];
    float up = (y > 0)      ? g_avg[idx - WW] : 0.f;
    float dn = (y < HH-1)   ? g_avg[idx + WW] : 0.f;
    float lf = (xq > 0)     ? g_avg[idx - 1]  : 0.f;
    float rt = (xq < WW-1)  ? g_avg[idx + 1]  : 0.f;
    float df = fabsf(4.f*c - up - dn - lf - rt);
    g_df[idx] = df;

    __shared__ float smn[256], smx[256];
    smn[tid] = df; smx[tid] = df;
    __syncthreads();
    for (int s = 128; s; s >>= 1) {
        if (tid < s) {
            smn[tid] = fminf(smn[tid], smn[tid+s]);
            smx[tid] = fmaxf(smx[tid], smx[tid+s]);
        }
        __syncthreads();
    }
    if (tid == 0) { g_pmn[blockIdx.x] = smn[0]; g_pmx[blockIdx.x] = smx[0]; }
}

// ======= K3: FUSED IPG core + GroupNorm + FFN (single kernel) ================
#define TW 32
#define TH 4
#define ROWW 34          // TW+2
#define TILE2 204        // (TH+2)*ROWW
#define PSTR 12          // words per position: 8 ch + 4 pad
#define NPIX 128         // pixels per CTA
#define ESTR 68          // Es words per pixel row (64 k-pairs + 4 pad)
#define HSTR 132         // Hs words per pixel row (128 k-pairs + 4 pad)
#define STSZ (2*2*TILE2*PSTR)   // 9792 floats for s_t
#define SMEM_FUSED ((128*ESTR + STSZ) * 4)

#define CE(a_,b_) do { \
    if ((sv[b_] > sv[a_]) || (sv[b_] == sv[a_] && si[b_] < si[a_])) { \
        float t_ = sv[a_]; sv[a_] = sv[b_]; sv[b_] = t_; \
        int u_ = si[a_]; si[a_] = si[b_]; si[b_] = u_; } \
} while (0)

#define MMA_BF16(C, A, B2) asm volatile( \
    "mma.sync.aligned.m16n8k16.row.col.f32.bf16.bf16.f32 " \
    "{%0,%1,%2,%3}, {%4,%5,%6,%7}, {%8,%9}, {%0,%1,%2,%3};\n" \
    : "+f"((C)[0]), "+f"((C)[1]), "+f"((C)[2]), "+f"((C)[3]) \
    : "r"((A)[0]), "r"((A)[1]), "r"((A)[2]), "r"((A)[3]), \
      "r"((B2)[0]), "r"((B2)[1]))

__global__ void __launch_bounds__(256, 2) k_fused(const float* __restrict__ x,
                                                  const float* __restrict__ gnw,
                                                  const float* __restrict__ gnb,
                                                  const float* __restrict__ b1,
                                                  const float* __restrict__ b2,
                                                  float* __restrict__ out) {
    extern __shared__ float sm[];
    unsigned* EsU = (unsigned*)sm;             // [128][ESTR]
    float*    s_t = sm + 128*ESTR;             // union: s_t | Hs
    unsigned* HsU = (unsigned*)(sm + 128*ESTR);

    __shared__ float s_red[NPIX][10];
    __shared__ float s_inv[TILE2];
    __shared__ float s_mean[NG], s_istd[NG];
    __shared__ float s_gnw[CC], s_gnb[CC];
    __shared__ float s_mn, s_mx;

    int b = blockIdx.z;
    int x0 = blockIdx.x * TW, y0 = blockIdx.y * TH;
    int tx = threadIdx.x, ty = threadIdx.y, zz = threadIdx.z;
    int tid = ty * TW + tx;                 // pixel 0..127
    int ft  = zz * NPIX + tid;              // flat 0..255

    // inline GN-stat reduction
    if (ft < NG) {
        float s = 0.f, ss = 0.f;
        for (int l = 0; l < BPB; l++) {
            s  += g_ps [(b*BPB + l)*NG + ft];
            ss += g_pss[(b*BPB + l)*NG + ft];
        }
        const float N = (float)(CPG * PP);
        float mean = s / N;
        s_mean[ft] = mean;
        s_istd[ft] = rsqrtf(ss / N - mean*mean + 1e-5f);
    } else if (ft == NG) {
        float mn = g_pmn[b*BPB];
        for (int l = 1; l < BPB; l++) mn = fminf(mn, g_pmn[b*BPB + l]);
        s_mn = mn;
    } else if (ft == NG + 1) {
        float mx = g_pmx[b*BPB];
        for (int l = 1; l < BPB; l++) mx = fmaxf(mx, g_pmx[b*BPB + l]);
        s_mx = mx;
    }
    if (ft < CC) { s_gnw[ft] = gnw[ft]; s_gnb[ft] = gnb[ft]; }

    // reflected global offsets for this half's fill positions
    int gp[2];
    #pragma unroll
    for (int j = 0; j < 2; j++) {
        int i = tid + NPIX*j;
        if (i < TILE2) {
            int yy = i / ROWW, xx = i - yy*ROWW;
            gp[j] = refl(y0 + yy - 1)*WW + refl(x0 + xx - 1);
        }
    }
    if (zz == 0) {
        #pragma unroll
        for (int j = 0; j < 2; j++) {
            int i = tid + NPIX*j;
            if (i < TILE2) s_inv[i] = g_invn[b*PP + gp[j]];
        }
    }

    const float* xbase = x + (size_t)(b*CC + zz*64) * PP;  // this half's channels

    float pv[2][8];
    auto ldchunk = [&](int ch) {
        const float* xb = xbase + (size_t)(ch*8) * PP;
        #pragma unroll
        for (int j = 0; j < 2; j++) {
            int i = tid + NPIX*j;
            if (i < TILE2) {
                #pragma unroll
                for (int c = 0; c < 8; c++) pv[j][c] = xb[(size_t)c*PP + gp[j]];
            }
        }
    };
    auto stchunk = [&](int buf) {
        #pragma unroll
        for (int j = 0; j < 2; j++) {
            int i = tid + NPIX*j;
            if (i < TILE2) {
                float4 a  = make_float4(pv[j][0], pv[j][1], pv[j][2], pv[j][3]);
                float4 c4 = make_float4(pv[j][4], pv[j][5], pv[j][6], pv[j][7]);
                *(float4*)&s_t[(zz*2 + buf)*(TILE2*PSTR) + i*PSTR]     = a;
                *(float4*)&s_t[(zz*2 + buf)*(TILE2*PSTR) + i*PSTR + 4] = c4;
            }
        }
    };

    int base9[9];
    #pragma unroll
    for (int dy = 0; dy < 3; dy++)
        #pragma unroll
        for (int dx = 0; dx < 3; dx++)
            base9[dy*3+dx] = ((ty+dy)*ROWW + tx+dx)*PSTR;

    // ---------------- pass 1: partial dots over this half's 64 channels ------
    float dots[9];
    #pragma unroll
    for (int j = 0; j < 9; j++) dots[j] = 0.f;

    ldchunk(0); stchunk(0);
    __syncthreads();
    for (int ch = 0; ch < 8; ch++) {
        int cur = ch & 1;
        if (ch < 7) ldchunk(ch + 1);
        #pragma unroll
        for (int half = 0; half < 2; half++) {
            float4 t9[9];
            #pragma unroll
            for (int j = 0; j < 9; j++)
                t9[j] = *(float4*)&s_t[(zz*2 + cur)*(TILE2*PSTR) + base9[j] + half*4];
            float4 v = t9[4];
            #pragma unroll
            for (int j = 0; j < 9; j++)
                dots[j] += v.x*t9[j].x + v.y*t9[j].y + v.z*t9[j].z + v.w*t9[j].w;
        }
        if (ch < 7) stchunk(cur ^ 1);
        __syncthreads();
    }

    // combine halves
    if (zz == 1) {
        #pragma unroll
        for (int j = 0; j < 9; j++) s_red[tid][j] = dots[j];
    }
    __syncthreads();
    if (zz == 0) {
        #pragma unroll
        for (int j = 0; j < 9; j++) { dots[j] += s_red[tid][j]; s_red[tid][j] = dots[j]; }
    }
    __syncthreads();
    if (zz == 1) {
        #pragma unroll
        for (int j = 0; j < 9; j++) dots[j] = s_red[tid][j];
    }

    float invc = s_inv[(ty+1)*ROWW + tx + 1];
    float sims[9];
    #pragma unroll
    for (int j = 0; j < 9; j++) {
        int dy = j / 3, dx = j - dy*3;
        sims[j] = dots[j] * invc * s_inv[(ty+dy)*ROWW + tx + dx];
    }

    int p = (y0 + ty) * WW + x0 + tx;
    float df = g_df[b*PP + p];
    float dn = (df - s_mn) / (s_mx - s_mn + 1e-8f);
    int k = 1 + (int)rintf(dn * 7.f);
    if (k < 1) k = 1; if (k > 8) k = 8;

    float sv[9]; int si[9];
    #pragma unroll
    for (int j = 0; j < 9; j++) { sv[j] = sims[j]; si[j] = j; }
    CE(0,3); CE(1,7); CE(2,5); CE(4,8);
    CE(0,7); CE(2,4); CE(3,8); CE(5,6);
    CE(0,2); CE(1,3); CE(4,5); CE(7,8);
    CE(1,4); CE(3,6); CE(5,7);
    CE(0,1); CE(2,4); CE(3,5); CE(6,8);
    CE(2,3); CE(4,5); CE(6,7);
    CE(1,2); CE(3,4); CE(5,6);

    float ts = sv[0]; int tix = si[0];
    #pragma unroll
    for (int r = 0; r < 9; r++) { if (r == k-1) { ts = sv[r]; tix = si[r]; } }

    float wj[9]; float ws = 0.f;
    #pragma unroll
    for (int j = 0; j < 9; j++) {
        bool sel = (sims[j] > ts) || (sims[j] == ts && j <= tix);
        wj[j] = sel ? expf(sims[j]) : 0.f;
        ws += wj[j];
    }
    float iws = 1.f / ws;
    #pragma unroll
    for (int j = 0; j < 9; j++) wj[j] *= iws;

    // ---- pass 2: enhanced -> out (fp32, residual) + Es (bf16 pairs) ---------
    ldchunk(0); stchunk(0);
    __syncthreads();
    for (int ch = 0; ch < 8; ch++) {
        int cur = ch & 1;
        if (ch < 7) ldchunk(ch + 1);
        int gidx = zz*8 + ch;
        float gm = s_mean[gidx], gi = s_istd[gidx];
        unsigned wbuf[4];
        #pragma unroll
        for (int half = 0; half < 2; half++) {
            float4 t9[9];
            #pragma unroll
            for (int j = 0; j < 9; j++)
                t9[j] = *(float4*)&s_t[(zz*2 + cur)*(TILE2*PSTR) + base9[j] + half*4];
            float4 acc = make_float4(0.f, 0.f, 0.f, 0.f);
            #pragma unroll
            for (int j = 0; j < 9; j++) {
                acc.x += wj[j]*t9[j].x; acc.y += wj[j]*t9[j].y;
                acc.z += wj[j]*t9[j].z; acc.w += wj[j]*t9[j].w;
            }
            float4 ctr = t9[4];
            int c = zz*64 + ch*8 + half*4;
            float e0 = acc.x + (ctr.x - gm)*gi*s_gnw[c]   + s_gnb[c];
            float e1 = acc.y + (ctr.y - gm)*gi*s_gnw[c+1] + s_gnb[c+1];
            float e2 = acc.z + (ctr.z - gm)*gi*s_gnw[c+2] + s_gnb[c+2];
            float e3 = acc.w + (ctr.w - gm)*gi*s_gnw[c+3] + s_gnb[c+3];
            float* dst = &out[(size_t)(b*CC + c) * PP + p];
            dst[0] = e0; dst[PP] = e1; dst[2*PP] = e2; dst[3*PP] = e3;
            wbuf[half*2]     = packbf(e0, e1);
            wbuf[half*2 + 1] = packbf(e2, e3);
        }
        *(uint4*)&EsU[tid*ESTR + zz*32 + ch*4] = *(uint4*)wbuf;
        if (ch < 7) stchunk(cur ^ 1);
        __syncthreads();
    }
    // s_t now dead; EsU complete and visible. Union region becomes Hs.

    // ==================== FFN phase (two 64-pixel halves) ====================
    int warp = ft >> 5, lane = ft & 31;
    int lm = lane >> 2, lk = lane & 3;

    for (int h = 0; h < 2; h++) {
        const unsigned* EsH = EsU + h*64*ESTR;

        // ---- GEMM1: 8 warps, warp tile 32(M) x 64(N) ----
        int wm1 = warp * 32;
        int m16a = warp * 2;
        float c1[2][8][4];
        #pragma unroll
        for (int mt = 0; mt < 2; mt++)
            #pragma unroll
            for (int nt = 0; nt < 8; nt++)
                #pragma unroll
                for (int q = 0; q < 4; q++) c1[mt][nt][q] = 0.f;

        #pragma unroll
        for (int st = 0; st < 8; st++) {
            int kw = st * 8;
            unsigned a[2][4], bw[8][2];
            *(uint4*)a[0] = g_w1f[((m16a    )*8 + st)*32 + lane];
            *(uint4*)a[1] = g_w1f[((m16a + 1)*8 + st)*32 + lane];
            #pragma unroll
            for (int nt = 0; nt < 8; nt++) {
                int nc = nt*8 + lm;
                bw[nt][0] = EsH[nc*ESTR + kw + lk];
                bw[nt][1] = EsH[nc*ESTR + kw + 4 + lk];
            }
            #pragma unroll
            for (int mt = 0; mt < 2; mt++)
                #pragma unroll
                for (int nt = 0; nt < 8; nt++)
                    MMA_BF16(c1[mt][nt], a[mt], bw[nt]);
        }

        // ---- H: bias + relu, pack row pairs via shfl, store n-major bf16 ----
        #pragma unroll
        for (int mt = 0; mt < 2; mt++) {
            int mr = wm1 + mt*16 + lm;
            float bi0 = b1[mr], bi1 = b1[mr + 8];
            #pragma unroll
            for (int nt = 0; nt < 8; nt++) {
                float v0 = fmaxf(c1[mt][nt][0] + bi0, 0.f);
                float v1 = fmaxf(c1[mt][nt][1] + bi0, 0.f);
                float v2 = fmaxf(c1[mt][nt][2] + bi1, 0.f);
                float v3 = fmaxf(c1[mt][nt][3] + bi1, 0.f);
                float p0 = __shfl_xor_sync(0xffffffffu, v0, 4);
                float p1 = __shfl_xor_sync(0xffffffffu, v1, 4);
                float p2 = __shfl_xor_sync(0xffffffffu, v2, 4);
                float p3 = __shfl_xor_sync(0xffffffffu, v3, 4);
                if (!(lm & 1)) {
                    int colA = nt*8 + 2*lk;
                    int w0 = mr >> 1;
                    HsU[colA    *HSTR + w0]     = packbf(v0, p0);
                    HsU[(colA+1)*HSTR + w0]     = packbf(v1, p1);
                    HsU[colA    *HSTR + w0 + 4] = packbf(v2, p2);
                    HsU[(colA+1)*HSTR + w0 + 4] = packbf(v3, p3);
                }
            }
        }
        __syncthreads();

        // ---- GEMM2: 8 warps, warp tile 16(M) x 64(N), K=256 ----
        int wm2 = warp * 16;
        int m16b = warp;
        float c2[8][4];
        #pragma unroll
        for (int nt = 0; nt < 8; nt++)
            #pragma unroll
            for (int q = 0; q < 4; q++) c2[nt][q] = 0.f;

        #pragma unroll
        for (int st = 0; st < 16; st++) {
            int kw = st * 8;
            unsigned a[4], bw[8][2];
            *(uint4*)a = g_w2f[(m16b*16 + st)*32 + lane];
            #pragma unroll
            for (int nt = 0; nt < 8; nt++) {
                int nc = nt*8 + lm;
                bw[nt][0] = HsU[nc*HSTR + kw + lk];
                bw[nt][1] = HsU[nc*HSTR + kw + 4 + lk];
            }
            #pragma unroll
            for (int nt = 0; nt < 8; nt++)
                MMA_BF16(c2[nt], a, bw[nt]);
        }

        // ---- epilogue: out = E(parked) + ffn + b2 ----
        {
            int mr = wm2 + lm;
            float bi0 = b2[mr], bi1 = b2[mr + 8];
            #pragma unroll
            for (int nt = 0; nt < 8; nt++) {
                int col = nt*8 + 2*lk;
                int lp = h*64 + col;
                int p0 = (y0 + (lp >> 5))*WW + x0 + (lp & 31);
                size_t o0 = (size_t)(b*CC + mr) * PP + p0;
                size_t o1 = o0 + (size_t)8 * PP;
                float2 e0 = *(const float2*)&out[o0];
                float2 e1 = *(const float2*)&out[o1];
                float2 v0, v1;
                v0.x = c2[nt][0] + bi0 + e0.x;
                v0.y = c2[nt][1] + bi0 + e0.y;
                v1.x = c2[nt][2] + bi1 + e1.x;
                v1.y = c2[nt][3] + bi1 + e1.y;
                *(float2*)&out[o0] = v0;
                *(float2*)&out[o1] = v1;
            }
        }
        __syncthreads();   // Hs free for next half
    }
}

// ---------------- launch ----------------
extern "C" void kernel_launch(void* const* d_in, const int* in_sizes, int n_in,
                              void* d_out, int out_size) {
    const float* x   = (const float*)d_in[0];
    const float* gnw = (const float*)d_in[1];
    const float* gnb = (const float*)d_in[2];
    const float* w1  = (const float*)d_in[3];
    const float* b1  = (const float*)d_in[4];
    const float* w2  = (const float*)d_in[5];
    const float* b2  = (const float*)d_in[6];
    float* out = (float*)d_out;

    cudaFuncSetAttribute(k_fused, cudaFuncAttributeMaxDynamicSharedMemorySize, SMEM_FUSED);

    k_stats<<<NBLK + 32, 256>>>(x, w1, w2);            // +32 blocks: W->frag bf16
    k_df   <<<NBLK, 256>>>();
    k_fused<<<dim3(WW/TW, HH/TH, BB), dim3(TW, TH, 2), SMEM_FUSED>>>(
        x, gnw, gnb, b1, b2, out);
}

// round 17
// speedup vs baseline: 1.1616x; 1.0415x over previous
#include <cuda_runtime.h>
#include <cuda_bf16.h>
#include <math.h>
#include <stdint.h>

// Problem constants
#define BB 8
#define CC 128
#define HH 96
#define WW 96
#define PP (HH*WW)       // 9216
#define NG 16            // groups
#define CPG 8            // channels per group
#define NBLK 288         // pixel-block count (BB*PP/256)
#define BPB 36           // pixel-blocks per batch
#define NBS2 (2*NBLK)    // stats blocks (channel-split)
#define BBPP (BB*PP)

// ---------------- scratch (device globals; no allocs allowed) ----------------
__device__ float g_sh [2*BBPP];            // partial per-pixel channel sums (halves)
__device__ float g_qh [2*BBPP];            // partial per-pixel sumsq (halves)
__device__ float g_df  [BBPP];
__device__ float g_ps  [NBLK*NG];
__device__ float g_pss [NBLK*NG];
__device__ float g_pmn [NBLK];
__device__ float g_pmx [NBLK];
__device__ uint4 g_w1f [16*8*32];          // w1 bf16x2 in mma-fragment order
__device__ uint4 g_w2f [8*16*32];          // w2 bf16x2 in mma-fragment order

__device__ __forceinline__ int refl(int i) {
    return i < 0 ? -i : (i >= HH ? 2*HH - 2 - i : i);
}

__device__ __forceinline__ unsigned packbf(float lo, float hi) {
    unsigned d;
    asm("cvt.rn.bf16x2.f32 %0, %1, %2;" : "=r"(d) : "f"(hi), "f"(lo));
    return d;
}

// ---------------- K1: channel-split stats (576 blocks, 64 ch each) -----------
// blocks >= NBS2 convert w1/w2 to bf16x2 fragment layout instead.
__global__ void k_stats(const float* __restrict__ x,
                        const float* __restrict__ w1,
                        const float* __restrict__ w2) {
    int tid = threadIdx.x;
    if (blockIdx.x >= NBS2) {
        int idx = (blockIdx.x - NBS2) * 256 + tid;     // 0..8191
        int lane = idx & 31, lk = lane & 3, lm = lane >> 2;
        int kw;
        if (idx < 4096) {                              // w1: 16 m-groups x 8 steps
            int m16 = idx >> 8, st = (idx >> 5) & 7;
            int mr = m16*16 + lm; kw = st*8;
            uint4 v;
            v.x = packbf(w1[mr*128     + 2*(kw+lk)],   w1[mr*128     + 2*(kw+lk)+1]);
            v.y = packbf(w1[(mr+8)*128 + 2*(kw+lk)],   w1[(mr+8)*128 + 2*(kw+lk)+1]);
            v.z = packbf(w1[mr*128     + 2*(kw+4+lk)], w1[mr*128     + 2*(kw+4+lk)+1]);
            v.w = packbf(w1[(mr+8)*128 + 2*(kw+4+lk)], w1[(mr+8)*128 + 2*(kw+4+lk)+1]);
            g_w1f[idx] = v;
        } else {                                       // w2: 8 m-groups x 16 steps
            int j = idx - 4096;
            int m16 = j >> 9, st = (j >> 5) & 15;
            int mr = m16*16 + lm; kw = st*8;
            uint4 v;
            v.x = packbf(w2[mr*256     + 2*(kw+lk)],   w2[mr*256     + 2*(kw+lk)+1]);
            v.y = packbf(w2[(mr+8)*256 + 2*(kw+lk)],   w2[(mr+8)*256 + 2*(kw+lk)+1]);
            v.z = packbf(w2[mr*256     + 2*(kw+4+lk)], w2[mr*256     + 2*(kw+4+lk)+1]);
            v.w = packbf(w2[(mr+8)*256 + 2*(kw+4+lk)], w2[(mr+8)*256 + 2*(kw+4+lk)+1]);
            g_w2f[j] = v;
        }
        return;
    }

    int pixblk = blockIdx.x >> 1;            // 0..287
    int zz = blockIdx.x & 1;                 // channel half
    int idx = pixblk * 256 + tid;            // (b,p)
    int b = idx / PP;
    const float* xb = x + (size_t)(b*CC + zz*64) * PP + (idx - b*PP);
    int lane = tid & 31;

    __shared__ float s_gs[8], s_gss[8];
    if (tid < 8) { s_gs[tid] = 0.f; s_gss[tid] = 0.f; }
    __syncthreads();

    float sum = 0.f, ssq = 0.f;
    float gsA[8], gssA[8];
    #pragma unroll
    for (int g = 0; g < 8; g++) {
        float gs = 0.f, gss = 0.f;
        #pragma unroll
        for (int cc = 0; cc < CPG; cc++) {
            float v = xb[(size_t)(g*CPG + cc) * PP];
            gs += v; gss += v*v;
        }
        sum += gs; ssq += gss;
        gsA[g] = gs; gssA[g] = gss;
    }

    g_sh[zz*BBPP + idx] = sum;
    g_qh[zz*BBPP + idx] = ssq;

    // deferred group reductions
    #pragma unroll
    for (int g = 0; g < 8; g++) {
        float gs = gsA[g], gss = gssA[g];
        #pragma unroll
        for (int off = 16; off; off >>= 1) {
            gs  += __shfl_xor_sync(0xffffffffu, gs,  off);
            gss += __shfl_xor_sync(0xffffffffu, gss, off);
        }
        if (lane == 0) { atomicAdd(&s_gs[g], gs); atomicAdd(&s_gss[g], gss); }
    }
    __syncthreads();
    if (tid < 8) {
        g_ps [pixblk*NG + zz*8 + tid] = s_gs [tid];
        g_pss[pixblk*NG + zz*8 + tid] = s_gss[tid];
    }
}

// ---------------- K2: laplacian of avg (zero pad), per-block min/max ---------
__device__ __forceinline__ float avg_at(int i) {
    return (g_sh[i] + g_sh[BBPP + i]) * (1.f/128.f);
}

__global__ void k_df() {
    int tid = threadIdx.x;
    int idx = blockIdx.x * 256 + tid;
    int b = idx / PP;
    int p = idx - b*PP;
    int y = p / WW, xq = p - y*WW;
    float c = avg_at(idx);
    float up = (y > 0)      ? avg_at(idx - WW) : 0.f;
    float dn = (y < HH-1)   ? avg_at(idx + WW) : 0.f;
    float lf = (xq > 0)     ? avg_at(idx - 1)  : 0.f;
    float rt = (xq < WW-1)  ? avg_at(idx + 1)  : 0.f;
    float df = fabsf(4.f*c - up - dn - lf - rt);
    g_df[idx] = df;

    __shared__ float smn[256], smx[256];
    smn[tid] = df; smx[tid] = df;
    __syncthreads();
    for (int s = 128; s; s >>= 1) {
        if (tid < s) {
            smn[tid] = fminf(smn[tid], smn[tid+s]);
            smx[tid] = fmaxf(smx[tid], smx[tid+s]);
        }
        __syncthreads();
    }
    if (tid == 0) { g_pmn[blockIdx.x] = smn[0]; g_pmx[blockIdx.x] = smx[0]; }
}

// ======= K3: FUSED IPG core + GroupNorm + FFN (single kernel) ================
#define TW 32
#define TH 4
#define ROWW 34          // TW+2
#define TILE2 204        // (TH+2)*ROWW
#define PSTR 12          // words per position: 8 ch + 4 pad
#define NPIX 128         // pixels per CTA
#define ESTR 68          // Es words per pixel row (64 k-pairs + 4 pad)
#define HSTR 132         // Hs words per pixel row (128 k-pairs + 4 pad)
#define STSZ (2*2*TILE2*PSTR)   // 9792 floats for s_t
#define SMEM_FUSED ((128*ESTR + STSZ) * 4)

#define CE(a_,b_) do { \
    if ((sv[b_] > sv[a_]) || (sv[b_] == sv[a_] && si[b_] < si[a_])) { \
        float t_ = sv[a_]; sv[a_] = sv[b_]; sv[b_] = t_; \
        int u_ = si[a_]; si[a_] = si[b_]; si[b_] = u_; } \
} while (0)

#define MMA_BF16(C, A, B2) asm volatile( \
    "mma.sync.aligned.m16n8k16.row.col.f32.bf16.bf16.f32 " \
    "{%0,%1,%2,%3}, {%4,%5,%6,%7}, {%8,%9}, {%0,%1,%2,%3};\n" \
    : "+f"((C)[0]), "+f"((C)[1]), "+f"((C)[2]), "+f"((C)[3]) \
    : "r"((A)[0]), "r"((A)[1]), "r"((A)[2]), "r"((A)[3]), \
      "r"((B2)[0]), "r"((B2)[1]))

__global__ void __launch_bounds__(256, 2) k_fused(const float* __restrict__ x,
                                                  const float* __restrict__ gnw,
                                                  const float* __restrict__ gnb,
                                                  const float* __restrict__ b1,
                                                  const float* __restrict__ b2,
                                                  float* __restrict__ out) {
    extern __shared__ float sm[];
    unsigned* EsU = (unsigned*)sm;             // [128][ESTR]
    float*    s_t = sm + 128*ESTR;             // union: s_t | Hs
    unsigned* HsU = (unsigned*)(sm + 128*ESTR);

    __shared__ float s_red[NPIX][10];
    __shared__ float s_inv[TILE2];
    __shared__ float s_mean[NG], s_istd[NG];
    __shared__ float s_gnw[CC], s_gnb[CC];
    __shared__ float s_mn, s_mx;

    int b = blockIdx.z;
    int x0 = blockIdx.x * TW, y0 = blockIdx.y * TH;
    int tx = threadIdx.x, ty = threadIdx.y, zz = threadIdx.z;
    int tid = ty * TW + tx;                 // pixel 0..127
    int ft  = zz * NPIX + tid;              // flat 0..255

    // inline GN-stat reduction
    if (ft < NG) {
        float s = 0.f, ss = 0.f;
        for (int l = 0; l < BPB; l++) {
            s  += g_ps [(b*BPB + l)*NG + ft];
            ss += g_pss[(b*BPB + l)*NG + ft];
        }
        const float N = (float)(CPG * PP);
        float mean = s / N;
        s_mean[ft] = mean;
        s_istd[ft] = rsqrtf(ss / N - mean*mean + 1e-5f);
    } else if (ft == NG) {
        float mn = g_pmn[b*BPB];
        for (int l = 1; l < BPB; l++) mn = fminf(mn, g_pmn[b*BPB + l]);
        s_mn = mn;
    } else if (ft == NG + 1) {
        float mx = g_pmx[b*BPB];
        for (int l = 1; l < BPB; l++) mx = fmaxf(mx, g_pmx[b*BPB + l]);
        s_mx = mx;
    }
    if (ft < CC) { s_gnw[ft] = gnw[ft]; s_gnb[ft] = gnb[ft]; }

    // reflected global offsets for this half's fill positions
    int gp[2];
    #pragma unroll
    for (int j = 0; j < 2; j++) {
        int i = tid + NPIX*j;
        if (i < TILE2) {
            int yy = i / ROWW, xx = i - yy*ROWW;
            gp[j] = refl(y0 + yy - 1)*WW + refl(x0 + xx - 1);
        }
    }
    if (zz == 0) {
        #pragma unroll
        for (int j = 0; j < 2; j++) {
            int i = tid + NPIX*j;
            if (i < TILE2) {
                int off = b*PP + gp[j];
                float q = g_qh[off] + g_qh[BBPP + off];
                s_inv[i] = 1.f / fmaxf(sqrtf(q), 1e-12f);
            }
        }
    }

    const float* xbase = x + (size_t)(b*CC + zz*64) * PP;  // this half's channels

    float pv[2][8];
    auto ldchunk = [&](int ch) {
        const float* xb = xbase + (size_t)(ch*8) * PP;
        #pragma unroll
        for (int j = 0; j < 2; j++) {
            int i = tid + NPIX*j;
            if (i < TILE2) {
                #pragma unroll
                for (int c = 0; c < 8; c++) pv[j][c] = xb[(size_t)c*PP + gp[j]];
            }
        }
    };
    auto stchunk = [&](int buf) {
        #pragma unroll
        for (int j = 0; j < 2; j++) {
            int i = tid + NPIX*j;
            if (i < TILE2) {
                float4 a  = make_float4(pv[j][0], pv[j][1], pv[j][2], pv[j][3]);
                float4 c4 = make_float4(pv[j][4], pv[j][5], pv[j][6], pv[j][7]);
                *(float4*)&s_t[(zz*2 + buf)*(TILE2*PSTR) + i*PSTR]     = a;
                *(float4*)&s_t[(zz*2 + buf)*(TILE2*PSTR) + i*PSTR + 4] = c4;
            }
        }
    };

    int base9[9];
    #pragma unroll
    for (int dy = 0; dy < 3; dy++)
        #pragma unroll
        for (int dx = 0; dx < 3; dx++)
            base9[dy*3+dx] = ((ty+dy)*ROWW + tx+dx)*PSTR;

    // ---------------- pass 1: partial dots over this half's 64 channels ------
    float dots[9];
    #pragma unroll
    for (int j = 0; j < 9; j++) dots[j] = 0.f;

    ldchunk(0); stchunk(0);
    __syncthreads();
    for (int ch = 0; ch < 8; ch++) {
        int cur = ch & 1;
        if (ch < 7) ldchunk(ch + 1);
        #pragma unroll
        for (int half = 0; half < 2; half++) {
            float4 t9[9];
            #pragma unroll
            for (int j = 0; j < 9; j++)
                t9[j] = *(float4*)&s_t[(zz*2 + cur)*(TILE2*PSTR) + base9[j] + half*4];
            float4 v = t9[4];
            #pragma unroll
            for (int j = 0; j < 9; j++)
                dots[j] += v.x*t9[j].x + v.y*t9[j].y + v.z*t9[j].z + v.w*t9[j].w;
        }
        if (ch < 7) stchunk(cur ^ 1);
        __syncthreads();
    }

    // combine halves
    if (zz == 1) {
        #pragma unroll
        for (int j = 0; j < 9; j++) s_red[tid][j] = dots[j];
    }
    __syncthreads();
    if (zz == 0) {
        #pragma unroll
        for (int j = 0; j < 9; j++) { dots[j] += s_red[tid][j]; s_red[tid][j] = dots[j]; }
    }
    __syncthreads();
    if (zz == 1) {
        #pragma unroll
        for (int j = 0; j < 9; j++) dots[j] = s_red[tid][j];
    }

    float invc = s_inv[(ty+1)*ROWW + tx + 1];
    float sims[9];
    #pragma unroll
    for (int j = 0; j < 9; j++) {
        int dy = j / 3, dx = j - dy*3;
        sims[j] = dots[j] * invc * s_inv[(ty+dy)*ROWW + tx + dx];
    }

    int p = (y0 + ty) * WW + x0 + tx;
    float df = g_df[b*PP + p];
    float dn = (df - s_mn) / (s_mx - s_mn + 1e-8f);
    int k = 1 + (int)rintf(dn * 7.f);
    if (k < 1) k = 1; if (k > 8) k = 8;

    float sv[9]; int si[9];
    #pragma unroll
    for (int j = 0; j < 9; j++) { sv[j] = sims[j]; si[j] = j; }
    CE(0,3); CE(1,7); CE(2,5); CE(4,8);
    CE(0,7); CE(2,4); CE(3,8); CE(5,6);
    CE(0,2); CE(1,3); CE(4,5); CE(7,8);
    CE(1,4); CE(3,6); CE(5,7);
    CE(0,1); CE(2,4); CE(3,5); CE(6,8);
    CE(2,3); CE(4,5); CE(6,7);
    CE(1,2); CE(3,4); CE(5,6);

    float ts = sv[0]; int tix = si[0];
    #pragma unroll
    for (int r = 0; r < 9; r++) { if (r == k-1) { ts = sv[r]; tix = si[r]; } }

    float wj[9]; float ws = 0.f;
    #pragma unroll
    for (int j = 0; j < 9; j++) {
        bool sel = (sims[j] > ts) || (sims[j] == ts && j <= tix);
        wj[j] = sel ? expf(sims[j]) : 0.f;
        ws += wj[j];
    }
    float iws = 1.f / ws;
    #pragma unroll
    for (int j = 0; j < 9; j++) wj[j] *= iws;

    // ---- pass 2: enhanced -> out (fp32, residual) + Es (bf16 pairs) ---------
    ldchunk(0); stchunk(0);
    __syncthreads();
    for (int ch = 0; ch < 8; ch++) {
        int cur = ch & 1;
        if (ch < 7) ldchunk(ch + 1);
        int gidx = zz*8 + ch;
        float gm = s_mean[gidx], gi = s_istd[gidx];
        unsigned wbuf[4];
        #pragma unroll
        for (int half = 0; half < 2; half++) {
            float4 t9[9];
            #pragma unroll
            for (int j = 0; j < 9; j++)
                t9[j] = *(float4*)&s_t[(zz*2 + cur)*(TILE2*PSTR) + base9[j] + half*4];
            float4 acc = make_float4(0.f, 0.f, 0.f, 0.f);
            #pragma unroll
            for (int j = 0; j < 9; j++) {
                acc.x += wj[j]*t9[j].x; acc.y += wj[j]*t9[j].y;
                acc.z += wj[j]*t9[j].z; acc.w += wj[j]*t9[j].w;
            }
            float4 ctr = t9[4];
            int c = zz*64 + ch*8 + half*4;
            float e0 = acc.x + (ctr.x - gm)*gi*s_gnw[c]   + s_gnb[c];
            float e1 = acc.y + (ctr.y - gm)*gi*s_gnw[c+1] + s_gnb[c+1];
            float e2 = acc.z + (ctr.z - gm)*gi*s_gnw[c+2] + s_gnb[c+2];
            float e3 = acc.w + (ctr.w - gm)*gi*s_gnw[c+3] + s_gnb[c+3];
            float* dst = &out[(size_t)(b*CC + c) * PP + p];
            dst[0] = e0; dst[PP] = e1; dst[2*PP] = e2; dst[3*PP] = e3;
            wbuf[half*2]     = packbf(e0, e1);
            wbuf[half*2 + 1] = packbf(e2, e3);
        }
        *(uint4*)&EsU[tid*ESTR + zz*32 + ch*4] = *(uint4*)wbuf;
        if (ch < 7) stchunk(cur ^ 1);
        __syncthreads();
    }
    // s_t now dead; EsU complete and visible. Union region becomes Hs.

    // ==================== FFN phase (two 64-pixel halves) ====================
    int warp = ft >> 5, lane = ft & 31;
    int lm = lane >> 2, lk = lane & 3;

    for (int h = 0; h < 2; h++) {
        const unsigned* EsH = EsU + h*64*ESTR;

        // ---- GEMM1: 8 warps, warp tile 32(M) x 64(N) ----
        int wm1 = warp * 32;
        int m16a = warp * 2;
        float c1[2][8][4];
        #pragma unroll
        for (int mt = 0; mt < 2; mt++)
            #pragma unroll
            for (int nt = 0; nt < 8; nt++)
                #pragma unroll
                for (int q = 0; q < 4; q++) c1[mt][nt][q] = 0.f;

        #pragma unroll
        for (int st = 0; st < 8; st++) {
            int kw = st * 8;
            unsigned a[2][4], bw[8][2];
            *(uint4*)a[0] = g_w1f[((m16a    )*8 + st)*32 + lane];
            *(uint4*)a[1] = g_w1f[((m16a + 1)*8 + st)*32 + lane];
            #pragma unroll
            for (int nt = 0; nt < 8; nt++) {
                int nc = nt*8 + lm;
                bw[nt][0] = EsH[nc*ESTR + kw + lk];
                bw[nt][1] = EsH[nc*ESTR + kw + 4 + lk];
            }
            #pragma unroll
            for (int mt = 0; mt < 2; mt++)
                #pragma unroll
                for (int nt = 0; nt < 8; nt++)
                    MMA_BF16(c1[mt][nt], a[mt], bw[nt]);
        }

        // ---- H: bias + relu, pack row pairs via shfl, store n-major bf16 ----
        #pragma unroll
        for (int mt = 0; mt < 2; mt++) {
            int mr = wm1 + mt*16 + lm;
            float bi0 = b1[mr], bi1 = b1[mr + 8];
            #pragma unroll
            for (int nt = 0; nt < 8; nt++) {
                float v0 = fmaxf(c1[mt][nt][0] + bi0, 0.f);
                float v1 = fmaxf(c1[mt][nt][1] + bi0, 0.f);
                float v2 = fmaxf(c1[mt][nt][2] + bi1, 0.f);
                float v3 = fmaxf(c1[mt][nt][3] + bi1, 0.f);
                float p0 = __shfl_xor_sync(0xffffffffu, v0, 4);
                float p1 = __shfl_xor_sync(0xffffffffu, v1, 4);
                float p2 = __shfl_xor_sync(0xffffffffu, v2, 4);
                float p3 = __shfl_xor_sync(0xffffffffu, v3, 4);
                if (!(lm & 1)) {
                    int colA = nt*8 + 2*lk;
                    int w0 = mr >> 1;
                    HsU[colA    *HSTR + w0]     = packbf(v0, p0);
                    HsU[(colA+1)*HSTR + w0]     = packbf(v1, p1);
                    HsU[colA    *HSTR + w0 + 4] = packbf(v2, p2);
                    HsU[(colA+1)*HSTR + w0 + 4] = packbf(v3, p3);
                }
            }
        }
        __syncthreads();

        // ---- GEMM2: 8 warps, warp tile 16(M) x 64(N), K=256 ----
        int wm2 = warp * 16;
        int m16b = warp;
        float c2[8][4];
        #pragma unroll
        for (int nt = 0; nt < 8; nt++)
            #pragma unroll
            for (int q = 0; q < 4; q++) c2[nt][q] = 0.f;

        #pragma unroll
        for (int st = 0; st < 16; st++) {
            int kw = st * 8;
            unsigned a[4], bw[8][2];
            *(uint4*)a = g_w2f[(m16b*16 + st)*32 + lane];
            #pragma unroll
            for (int nt = 0; nt < 8; nt++) {
                int nc = nt*8 + lm;
                bw[nt][0] = HsU[nc*HSTR + kw + lk];
                bw[nt][1] = HsU[nc*HSTR + kw + 4 + lk];
            }
            #pragma unroll
            for (int nt = 0; nt < 8; nt++)
                MMA_BF16(c2[nt], a, bw[nt]);
        }

        // ---- epilogue: out = E(parked) + ffn + b2 ----
        {
            int mr = wm2 + lm;
            float bi0 = b2[mr], bi1 = b2[mr + 8];
            #pragma unroll
            for (int nt = 0; nt < 8; nt++) {
                int col = nt*8 + 2*lk;
                int lp = h*64 + col;
                int p0 = (y0 + (lp >> 5))*WW + x0 + (lp & 31);
                size_t o0 = (size_t)(b*CC + mr) * PP + p0;
                size_t o1 = o0 + (size_t)8 * PP;
                float2 e0 = *(const float2*)&out[o0];
                float2 e1 = *(const float2*)&out[o1];
                float2 v0, v1;
                v0.x = c2[nt][0] + bi0 + e0.x;
                v0.y = c2[nt][1] + bi0 + e0.y;
                v1.x = c2[nt][2] + bi1 + e1.x;
                v1.y = c2[nt][3] + bi1 + e1.y;
                *(float2*)&out[o0] = v0;
                *(float2*)&out[o1] = v1;
            }
        }
        __syncthreads();   // Hs free for next half
    }
}

// ---------------- launch ----------------
extern "C" void kernel_launch(void* const* d_in, const int* in_sizes, int n_in,
                              void* d_out, int out_size) {
    const float* x   = (const float*)d_in[0];
    const float* gnw = (const float*)d_in[1];
    const float* gnb = (const float*)d_in[2];
    const float* w1  = (const float*)d_in[3];
    const float* b1  = (const float*)d_in[4];
    const float* w2  = (const float*)d_in[5];
    const float* b2  = (const float*)d_in[6];
    float* out = (float*)d_out;

    cudaFuncSetAttribute(k_fused, cudaFuncAttributeMaxDynamicSharedMemorySize, SMEM_FUSED);

    k_stats<<<NBS2 + 32, 256>>>(x, w1, w2);            // +32 blocks: W->frag bf16
    k_df   <<<NBLK, 256>>>();
    k_fused<<<dim3(WW/TW, HH/TH, BB), dim3(TW, TH, 2), SMEM_FUSED>>>(
        x, gnw, gnb, b1, b2, out);
}